// round 8
// baseline (speedup 1.0000x reference)
#include <cuda_runtime.h>
#include <cuda_bf16.h>
#include <cuda_fp16.h>
#include <cuda.h>
#include <cstdint>
#include <math.h>

// ---------------- problem constants ----------------
#define NF      16381
#define TS      8388608
#define XPAD    8390144      // 512*16387
#define FFTLEN  2048
#define HOP     512
#define NBINS   84
#define FB      1025
#define NTC     192          // padded N (2*84 -> 192)
#define KC      32
#define NCHUNK  (FFTLEN / KC)   // 64
#define TILE_M  64
#define GRID_M  256

// combine GEMM dims
#define KK      2176
#define KHALF   1088
#define NW      (NTC * FFTLEN)   // 393216
#define KSPLIT  16

typedef unsigned long long ull;
typedef __nv_bfloat16 bf16;
typedef __half fp16;

// ---------------- scratch ----------------
__device__ __align__(16) fp16  g_xh[XPAD];
__device__ __align__(16) fp16  g_Wf[NW];
__device__ __align__(16) bf16  g_Ah[2048 * KK];
__device__ __align__(16) bf16  g_Al[2048 * KK];
__device__ __align__(16) bf16  g_Bh[NTC * KK];
__device__ __align__(16) bf16  g_Bl[NTC * KK];
__device__ __align__(16) float g_Wpart[KSPLIT * NW];

// ---------------- base-ISA PTX helpers ----------------
__device__ __forceinline__ uint32_t smem_u32(const void* p) {
    uint32_t a;
    asm("{ .reg .u64 t; cvta.to.shared.u64 t, %1; cvt.u32.u64 %0, t; }" : "=r"(a) : "l"(p));
    return a;
}

#define MBAR_INIT(addr, cnt) \
    asm volatile("mbarrier.init.shared.b64 [%0], %1;" :: "r"((uint32_t)(addr)), "r"((uint32_t)(cnt)) : "memory")
#define MBAR_INVAL(addr) \
    asm volatile("mbarrier.inval.shared.b64 [%0];" :: "r"((uint32_t)(addr)) : "memory")
#define MBAR_ARRIVE(addr) \
    asm volatile("mbarrier.arrive.shared.b64 _, [%0];" :: "r"((uint32_t)(addr)) : "memory")
#define MBAR_EXPECT_TX(addr, bytes) \
    asm volatile("mbarrier.arrive.expect_tx.shared.b64 _, [%0], %1;" \
        :: "r"((uint32_t)(addr)), "r"((uint32_t)(bytes)) : "memory")

#define WAITP(mbar, ph) do { \
    uint32_t _m = (uint32_t)(mbar); uint32_t _p = (uint32_t)(ph); uint32_t _d; \
    asm volatile("{\n\t.reg .pred p;\n\t" \
        "mbarrier.try_wait.parity.acquire.cta.shared::cta.b64 p, [%1], %2;\n\t" \
        "selp.b32 %0, 1, 0, p;\n\t}" : "=r"(_d) : "r"(_m), "r"(_p) : "memory"); \
    if (!_d) { \
        asm volatile("{\n\t.reg .pred P1;\n\t" \
            "WL_%=:\n\t" \
            "mbarrier.try_wait.parity.acquire.cta.shared::cta.b64 P1, [%0], %1, 0x989680;\n\t" \
            "@P1 bra.uni WD_%=;\n\t" \
            "bra.uni WL_%=;\n\t" \
            "WD_%=:\n\t}" :: "r"(_m), "r"(_p) : "memory"); \
    } } while (0)

#define TMA2D(dst, map, x0, y0, mb) \
    asm volatile("cp.async.bulk.tensor.2d.shared::cta.global.tile.mbarrier::complete_tx::bytes " \
        "[%0], [%1, {%2, %3}], [%4];" \
        :: "r"((uint32_t)(dst)), "l"(map), "r"((int)(x0)), "r"((int)(y0)), "r"((uint32_t)(mb)) : "memory")

__device__ __forceinline__ void ldsm4(uint32_t* r, uint32_t addr) {
    asm volatile("ldmatrix.sync.aligned.m8n8.x4.shared.b16 {%0,%1,%2,%3}, [%4];"
        : "=r"(r[0]), "=r"(r[1]), "=r"(r[2]), "=r"(r[3]) : "r"(addr));
}
__device__ __forceinline__ void mma_bf16(float* c, const uint32_t* a, const uint32_t* b) {
    asm volatile("mma.sync.aligned.m16n8k16.row.col.f32.bf16.bf16.f32 "
        "{%0,%1,%2,%3}, {%4,%5,%6,%7}, {%8,%9}, {%0,%1,%2,%3};"
        : "+f"(c[0]), "+f"(c[1]), "+f"(c[2]), "+f"(c[3])
        : "r"(a[0]), "r"(a[1]), "r"(a[2]), "r"(a[3]), "r"(b[0]), "r"(b[1]));
}
__device__ __forceinline__ void mma_fp16(float* c, const uint32_t* a, const uint32_t* b) {
    asm volatile("mma.sync.aligned.m16n8k16.row.col.f32.f16.f16.f32 "
        "{%0,%1,%2,%3}, {%4,%5,%6,%7}, {%8,%9}, {%0,%1,%2,%3};"
        : "+f"(c[0]), "+f"(c[1]), "+f"(c[2]), "+f"(c[3])
        : "r"(a[0]), "r"(a[1]), "r"(a[2]), "r"(a[3]), "r"(b[0]), "r"(b[1]));
}

// ======================================================================
// Kernel 1 (merged prep): atrans | bbuild | xconvert in one launch
// ======================================================================
#define ATR_BLKS  4352          // 64 * 68
#define BB_BLKS   1728          // 9 * 192
#define XS_BLKS   8194
#define PREP_BLKS (ATR_BLKS + BB_BLKS + XS_BLKS)

__global__ __launch_bounds__(256) void prep_kernel(
    const float* __restrict__ x,
    const float* __restrict__ wcos, const float* __restrict__ wsin,
    const float* __restrict__ kr,   const float* __restrict__ ki)
{
    __shared__ float t[32][33];
    const int blk = blockIdx.x;
    const int tid = threadIdx.x;

    if (blk < ATR_BLKS) {
        const int tx = tid & 31, ty = tid >> 5;
        const int m0 = (blk & 63) * 32;
        const int bj = blk >> 6;
        const float* src;
        int srow0, kk0;
        if (bj < 34) { src = wcos; srow0 = bj * 32;        kk0 = bj * 32; }
        else         { src = wsin; srow0 = (bj - 34) * 32; kk0 = KHALF + (bj - 34) * 32; }
        #pragma unroll
        for (int i = 0; i < 4; i++) {
            const int r  = ty + i * 8;
            const int sr = srow0 + r;
            t[r][tx] = (sr < FB) ? src[sr * FFTLEN + m0 + tx] : 0.f;
        }
        __syncthreads();
        #pragma unroll
        for (int i = 0; i < 4; i++) {
            const int m = m0 + ty + i * 8;
            const float v = t[tx][ty + i * 8];
            bf16 h = __float2bfloat16(v);
            g_Ah[m * KK + kk0 + tx] = h;
            g_Al[m * KK + kk0 + tx] = __float2bfloat16(v - __bfloat162float(h));
        }
    } else if (blk < ATR_BLKS + BB_BLKS) {
        const int b2  = blk - ATR_BLKS;
        const int kk  = (b2 % 9) * 256 + tid;
        const int row = b2 / 9;
        if (kk >= KK) return;
        float v = 0.f;
        if (row < NBINS) {
            if (kk < FB)                             v =  kr[row * FB + kk];
            else if (kk >= KHALF && kk < KHALF + FB) v = -ki[row * FB + kk - KHALF];
        } else if (row < 2 * NBINS) {
            const int j = row - NBINS;
            if (kk < FB)                             v =  ki[j * FB + kk];
            else if (kk >= KHALF && kk < KHALF + FB) v =  kr[j * FB + kk - KHALF];
        }
        bf16 h = __float2bfloat16(v);
        g_Bh[row * KK + kk] = h;
        g_Bl[row * KK + kk] = __float2bfloat16(v - __bfloat162float(h));
    } else {
        const int i = ((blk - ATR_BLKS - BB_BLKS) * 256 + tid) * 4;
        if (i >= XPAD) return;
        float v[4];
        if (i + 4 <= TS) {
            float4 q = *(const float4*)(x + i);
            v[0] = q.x; v[1] = q.y; v[2] = q.z; v[3] = q.w;
        } else {
            #pragma unroll
            for (int j = 0; j < 4; j++) v[j] = (i + j < TS) ? x[i + j] : 0.f;
        }
        union { fp16 h[4]; uint2 u; } H;
        #pragma unroll
        for (int j = 0; j < 4; j++) H.h[j] = __float2half(v[j]);
        *(uint2*)&g_xh[i] = H.u;
    }
}

// ======================================================================
// Kernel 2: combine GEMM Wt = A' @ B'^T  (bf16 3-product), K-split x16
// ======================================================================
#define CSTAGE     3
#define CSTG_SZ    32768
#define CSTAGE0    1024
#define CSMEM      (CSTAGE0 + CSTAGE * CSTG_SZ)
#define CCHB       32768

__device__ __forceinline__ void issue_chunk_c(
    uint32_t sb, int s, int m0, int kc,
    const void* tAh, const void* tAl, const void* tBh, const void* tBl)
{
    const uint32_t mb = sb + s * 16;
    const uint32_t st = sb + CSTAGE0 + s * CSTG_SZ;
    MBAR_EXPECT_TX(mb, CCHB);
    TMA2D(st,         tAh, kc * 32, m0, mb);
    TMA2D(st + 4096,  tAl, kc * 32, m0, mb);
    TMA2D(st + 8192,  tBh, kc * 32, 0, mb);
    TMA2D(st + 20480, tBl, kc * 32, 0, mb);
}

__global__ __launch_bounds__(256, 2) void comb_mma_kernel(
    const __grid_constant__ CUtensorMap tmAh,
    const __grid_constant__ CUtensorMap tmAl,
    const __grid_constant__ CUtensorMap tmBh,
    const __grid_constant__ CUtensorMap tmBl)
{
    extern __shared__ __align__(1024) char smem[];
    const uint32_t sb = smem_u32(smem);
    const int tid  = threadIdx.x;
    const int wid  = tid >> 5;
    const int lane = tid & 31;
    const int wm   = wid & 1;
    const int wn   = wid >> 1;
    const int m0   = blockIdx.x * TILE_M;
    const int sp   = blockIdx.y;
    // 68 chunks over 16 splits: first 4 get 5, rest get 4
    const int nch  = (sp < 4) ? 5 : 4;
    const int ksb  = (sp < 4) ? sp * 5 : 20 + (sp - 4) * 4;

    const int arow  = wm * 32 + (lane & 15);
    const int akb   = (lane >> 4) * 16;
    const int aswz  = ((arow >> 1) & 3) << 4;
    const int abase = arow * 64;
    const int brown = (lane & 7) + ((lane & 16) ? 8 : 0);
    const int bkb   = (lane & 8) ? 16 : 0;
    const int bswz  = ((brown >> 1) & 3) << 4;
    const int bbase = (wn * 48 + brown) * 64;

    if (tid == 0) {
        #pragma unroll
        for (int s = 0; s < CSTAGE; s++) {
            MBAR_INIT(sb + s * 16, 1);
            MBAR_INIT(sb + s * 16 + 8, 256);
        }
    }
    __syncthreads();
    if (tid == 0) {
        #pragma unroll
        for (int s = 0; s < CSTAGE; s++)
            if (s < nch) issue_chunk_c(sb, s, m0, ksb + s, &tmAh, &tmAl, &tmBh, &tmBl);
    }

    float acc[2][6][4];
    #pragma unroll
    for (int t = 0; t < 2; t++)
        #pragma unroll
        for (int j = 0; j < 6; j++)
            #pragma unroll
            for (int q = 0; q < 4; q++) acc[t][j][q] = 0.f;

    int fph[CSTAGE] = {0, 0, 0};
    int eph[CSTAGE] = {0, 0, 0};

    for (int c = 0; c < nch; ++c) {
        const int s = c % CSTAGE;
        WAITP(sb + s * 16, fph[s]); fph[s] ^= 1;
        const uint32_t st = sb + CSTAGE0 + s * CSTG_SZ;

        #pragma unroll
        for (int ks = 0; ks < 2; ++ks) {
            uint32_t ah[2][4], alr[2][4], bh[6][2], blr[6][2];
            #pragma unroll
            for (int t = 0; t < 2; ++t) {
                const uint32_t ao = abase + t * 1024 + ((ks * 32 + akb) ^ aswz);
                ldsm4(ah[t],  st + ao);
                ldsm4(alr[t], st + 4096 + ao);
            }
            #pragma unroll
            for (int j2 = 0; j2 < 3; ++j2) {
                const uint32_t bo = bbase + j2 * 1024 + ((ks * 32 + bkb) ^ bswz);
                uint32_t r4[4];
                ldsm4(r4, st + 8192 + bo);
                bh[2*j2][0] = r4[0]; bh[2*j2][1] = r4[1];
                bh[2*j2+1][0] = r4[2]; bh[2*j2+1][1] = r4[3];
                ldsm4(r4, st + 20480 + bo);
                blr[2*j2][0] = r4[0]; blr[2*j2][1] = r4[1];
                blr[2*j2+1][0] = r4[2]; blr[2*j2+1][1] = r4[3];
            }
            #pragma unroll
            for (int t = 0; t < 2; ++t)
                #pragma unroll
                for (int j = 0; j < 6; ++j) {
                    mma_bf16(acc[t][j], ah[t],  bh[j]);
                    mma_bf16(acc[t][j], ah[t],  blr[j]);
                    mma_bf16(acc[t][j], alr[t], bh[j]);
                }
        }

        MBAR_ARRIVE(sb + s * 16 + 8);
        if (tid == 0 && c + CSTAGE < nch) {
            WAITP(sb + s * 16 + 8, eph[s]); eph[s] ^= 1;
            issue_chunk_c(sb, s, m0, ksb + c + CSTAGE, &tmAh, &tmAl, &tmBh, &tmBl);
        }
    }

    __syncthreads();
    float* Cs = (float*)(smem + CSTAGE0);   // [192][68]
    const int g  = lane >> 2;
    const int tc = lane & 3;
    #pragma unroll
    for (int t = 0; t < 2; ++t) {
        const int r0 = wm * 32 + t * 16 + g;
        #pragma unroll
        for (int j = 0; j < 6; ++j) {
            const int col = wn * 48 + j * 8 + tc * 2;
            Cs[col * 68 + r0]           = acc[t][j][0];
            Cs[(col + 1) * 68 + r0]     = acc[t][j][1];
            Cs[col * 68 + r0 + 8]       = acc[t][j][2];
            Cs[(col + 1) * 68 + r0 + 8] = acc[t][j][3];
        }
    }
    __syncthreads();
    float* dst = g_Wpart + sp * NW;
    #pragma unroll
    for (int i = tid; i < NTC * TILE_M; i += 256) {
        const int bin = i >> 6;
        const int r   = i & 63;
        dst[bin * FFTLEN + m0 + r] = Cs[bin * 68 + r];
    }

    __syncthreads();
    if (tid == 0) {
        #pragma unroll
        for (int s = 0; s < CSTAGE; s++) { MBAR_INVAL(sb + s * 16); MBAR_INVAL(sb + s * 16 + 8); }
    }
}

// ======================================================================
// Kernel 3: reduce 16 partials -> fp16 W
// ======================================================================
__global__ __launch_bounds__(256) void wconvert_kernel() {
    const int i = (blockIdx.x * 256 + threadIdx.x) * 4;
    if (i >= NW) return;
    float4 s = *(const float4*)&g_Wpart[i];
    #pragma unroll
    for (int p = 1; p < KSPLIT; p++) {
        float4 q = *(const float4*)&g_Wpart[p * NW + i];
        s.x += q.x; s.y += q.y; s.z += q.z; s.w += q.w;
    }
    union { fp16 h[4]; uint2 u; } H;
    H.h[0] = __float2half(s.x); H.h[1] = __float2half(s.y);
    H.h[2] = __float2half(s.z); H.h[3] = __float2half(s.w);
    *(uint2*)&g_Wf[i] = H.u;
}

// ======================================================================
// Kernel 4: main fp16 GEMM + magnitude, 384 threads (2 M x 6 N warps)
//   stage: A 4KB | B 12KB = 16KB, 6 stages, 2 CTAs/SM -> 24 warps/SM
// ======================================================================
#define MSTAGE   6
#define MSTG_SZ  16384
#define MSTAGE0  1024
#define MSMEM    (MSTAGE0 + MSTAGE * MSTG_SZ)   // 99328
#define MCHB     16384
#define MT       384

__device__ __forceinline__ void issue_chunk_m(
    uint32_t sb, int s, int f0, int c,
    const void* tX, const void* tW)
{
    const uint32_t mb = sb + s * 16;
    const uint32_t st = sb + MSTAGE0 + s * MSTG_SZ;
    const int kx = (c & 15) * 32;
    const int ky = f0 + (c >> 4);
    MBAR_EXPECT_TX(mb, MCHB);
    TMA2D(st,        tX, kx, ky, mb);
    TMA2D(st + 4096, tW, c * 32, 0, mb);
}

__global__ __launch_bounds__(MT, 2) void cqt_mma_kernel(
    const __grid_constant__ CUtensorMap tmX,
    const __grid_constant__ CUtensorMap tmW,
    float* __restrict__ out)
{
    extern __shared__ __align__(1024) char smem[];
    const uint32_t sb = smem_u32(smem);
    const int tid  = threadIdx.x;
    const int wid  = tid >> 5;
    const int lane = tid & 31;
    const int wm   = wid & 1;        // 2 m-warps
    const int wn   = wid >> 1;       // 6 n-warps, 32 cols each
    const int f0   = blockIdx.x * TILE_M;

    const int arow  = wm * 32 + (lane & 15);
    const int akb   = (lane >> 4) * 16;
    const int aswz  = ((arow >> 1) & 3) << 4;
    const int abase = arow * 64;
    const int brown = (lane & 7) + ((lane & 16) ? 8 : 0);
    const int bkb   = (lane & 8) ? 16 : 0;
    const int bswz  = ((brown >> 1) & 3) << 4;
    const int bbase = (wn * 32 + brown) * 64;

    if (tid == 0) {
        #pragma unroll
        for (int s = 0; s < MSTAGE; s++) {
            MBAR_INIT(sb + s * 16, 1);
            MBAR_INIT(sb + s * 16 + 8, MT);
        }
    }
    __syncthreads();
    if (tid == 0) {
        #pragma unroll
        for (int s = 0; s < MSTAGE; s++)
            issue_chunk_m(sb, s, f0, s, &tmX, &tmW);
    }

    float acc[2][4][4];
    #pragma unroll
    for (int t = 0; t < 2; t++)
        #pragma unroll
        for (int j = 0; j < 4; j++)
            #pragma unroll
            for (int q = 0; q < 4; q++) acc[t][j][q] = 0.f;

    int fph[MSTAGE] = {0, 0, 0, 0, 0, 0};
    int eph[MSTAGE] = {0, 0, 0, 0, 0, 0};

    for (int c = 0; c < NCHUNK; ++c) {
        const int s = c % MSTAGE;
        WAITP(sb + s * 16, fph[s]); fph[s] ^= 1;
        const uint32_t st = sb + MSTAGE0 + s * MSTG_SZ;

        #pragma unroll
        for (int ks = 0; ks < 2; ++ks) {
            uint32_t ah[2][4], bh[4][2];
            #pragma unroll
            for (int t = 0; t < 2; ++t) {
                const uint32_t ao = abase + t * 1024 + ((ks * 32 + akb) ^ aswz);
                ldsm4(ah[t], st + ao);
            }
            #pragma unroll
            for (int j2 = 0; j2 < 2; ++j2) {
                const uint32_t bo = bbase + j2 * 1024 + ((ks * 32 + bkb) ^ bswz);
                uint32_t r4[4];
                ldsm4(r4, st + 4096 + bo);
                bh[2*j2][0] = r4[0]; bh[2*j2][1] = r4[1];
                bh[2*j2+1][0] = r4[2]; bh[2*j2+1][1] = r4[3];
            }
            #pragma unroll
            for (int t = 0; t < 2; ++t)
                #pragma unroll
                for (int j = 0; j < 4; ++j)
                    mma_fp16(acc[t][j], ah[t], bh[j]);
        }

        MBAR_ARRIVE(sb + s * 16 + 8);
        if (tid == 0 && c + MSTAGE < NCHUNK) {
            WAITP(sb + s * 16 + 8, eph[s]); eph[s] ^= 1;
            issue_chunk_m(sb, s, f0, c + MSTAGE, &tmX, &tmW);
        }
    }

    // ---------------- epilogue ----------------
    __syncthreads();
    float* Cs = (float*)(smem + MSTAGE0);   // [192][68]
    const int g  = lane >> 2;
    const int tc = lane & 3;
    #pragma unroll
    for (int t = 0; t < 2; ++t) {
        const int r0 = wm * 32 + t * 16 + g;
        #pragma unroll
        for (int j = 0; j < 4; ++j) {
            const int col = wn * 32 + j * 8 + tc * 2;
            Cs[col * 68 + r0]           = acc[t][j][0];
            Cs[(col + 1) * 68 + r0]     = acc[t][j][1];
            Cs[col * 68 + r0 + 8]       = acc[t][j][2];
            Cs[(col + 1) * 68 + r0 + 8] = acc[t][j][3];
        }
    }
    __syncthreads();
    #pragma unroll
    for (int i = tid; i < NBINS * TILE_M; i += MT) {
        const int bin = i >> 6;
        const int r   = i & 63;
        const int f   = f0 + r;
        if (f < NF) {
            const float re = Cs[bin * 68 + r];
            const float im = Cs[(bin + NBINS) * 68 + r];
            out[bin * NF + f] = sqrtf(re * re + im * im);
        }
    }

    __syncthreads();
    if (tid == 0) {
        #pragma unroll
        for (int s = 0; s < MSTAGE; s++) { MBAR_INVAL(sb + s * 16); MBAR_INVAL(sb + s * 16 + 8); }
    }
}

// ======================================================================
// host side
// ======================================================================
typedef CUresult (CUDAAPI *EncodeFn)(
    CUtensorMap*, CUtensorMapDataType, cuuint32_t, void*,
    const cuuint64_t*, const cuuint64_t*, const cuuint32_t*, const cuuint32_t*,
    CUtensorMapInterleave, CUtensorMapSwizzle, CUtensorMapL2promotion,
    CUtensorMapFloatOOBfill);

static void encode_2d(EncodeFn enc, CUtensorMap* tm, void* ptr,
                      CUtensorMapDataType dt,
                      unsigned long long d0, unsigned long long d1,
                      unsigned long long strideB,
                      unsigned box0, unsigned box1) {
    cuuint64_t dims[2] = {d0, d1};
    cuuint64_t str[1]  = {strideB};
    cuuint32_t box[2]  = {box0, box1};
    cuuint32_t es[2]   = {1, 1};
    enc(tm, dt, 2, ptr, dims, str, box, es,
        CU_TENSOR_MAP_INTERLEAVE_NONE, CU_TENSOR_MAP_SWIZZLE_64B,
        CU_TENSOR_MAP_L2_PROMOTION_L2_128B, CU_TENSOR_MAP_FLOAT_OOB_FILL_NONE);
}

extern "C" void kernel_launch(void* const* d_in, const int* in_sizes, int n_in,
                              void* d_out, int out_size) {
    const float* x    = (const float*)d_in[0];
    const float* wcos = (const float*)d_in[1];
    const float* wsin = (const float*)d_in[2];
    const float* kr   = (const float*)d_in[3];
    const float* ki   = (const float*)d_in[4];
    float* out = (float*)d_out;

    void* fn = nullptr;
    cudaDriverEntryPointQueryResult st;
#if CUDART_VERSION >= 12050
    cudaGetDriverEntryPointByVersion("cuTensorMapEncodeTiled", &fn, 12000,
                                     cudaEnableDefault, &st);
#else
    cudaGetDriverEntryPoint("cuTensorMapEncodeTiled", &fn, cudaEnableDefault, &st);
#endif
    EncodeFn enc = (EncodeFn)fn;

    void *pxh, *pwf, *pah, *pal, *pbh, *pbl;
    cudaGetSymbolAddress(&pxh, g_xh);
    cudaGetSymbolAddress(&pwf, g_Wf);
    cudaGetSymbolAddress(&pah, g_Ah);
    cudaGetSymbolAddress(&pal, g_Al);
    cudaGetSymbolAddress(&pbh, g_Bh);
    cudaGetSymbolAddress(&pbl, g_Bl);

    CUtensorMap tmX, tmW, tmAh, tmAl, tmBh, tmBl;
    encode_2d(enc, &tmX, pxh, CU_TENSOR_MAP_DATA_TYPE_FLOAT16,
              512, 16387, 512ull * 2, 32, TILE_M);
    encode_2d(enc, &tmW, pwf, CU_TENSOR_MAP_DATA_TYPE_FLOAT16,
              FFTLEN, NTC, (unsigned long long)FFTLEN * 2, 32, NTC);
    encode_2d(enc, &tmAh, pah, CU_TENSOR_MAP_DATA_TYPE_BFLOAT16,
              KK, 2048, (unsigned long long)KK * 2, 32, TILE_M);
    encode_2d(enc, &tmAl, pal, CU_TENSOR_MAP_DATA_TYPE_BFLOAT16,
              KK, 2048, (unsigned long long)KK * 2, 32, TILE_M);
    encode_2d(enc, &tmBh, pbh, CU_TENSOR_MAP_DATA_TYPE_BFLOAT16,
              KK, NTC, (unsigned long long)KK * 2, 32, NTC);
    encode_2d(enc, &tmBl, pbl, CU_TENSOR_MAP_DATA_TYPE_BFLOAT16,
              KK, NTC, (unsigned long long)KK * 2, 32, NTC);

    cudaFuncSetAttribute(cqt_mma_kernel,
                         cudaFuncAttributeMaxDynamicSharedMemorySize, MSMEM);
    cudaFuncSetAttribute(comb_mma_kernel,
                         cudaFuncAttributeMaxDynamicSharedMemorySize, CSMEM);

    prep_kernel<<<PREP_BLKS, 256>>>(x, wcos, wsin, kr, ki);
    comb_mma_kernel<<<dim3(32, KSPLIT), 256, CSMEM>>>(tmAh, tmAl, tmBh, tmBl);
    wconvert_kernel<<<NW / 1024, 256>>>();
    cqt_mma_kernel<<<GRID_M, MT, MSMEM>>>(tmX, tmW, out);
}

// round 10
// speedup vs baseline: 1.1380x; 1.1380x over previous
#include <cuda_runtime.h>
#include <cuda_bf16.h>
#include <cuda_fp16.h>
#include <cuda.h>
#include <cstdint>
#include <math.h>

// ---------------- problem constants ----------------
#define NF      16381
#define TS      8388608
#define XPAD    8390144      // 512*16387
#define FFTLEN  2048
#define HOP     512
#define NBINS   84
#define FB      1025
#define NTC     192          // padded N (2*84 -> 192)
#define KC      64
#define NCHUNK  (FFTLEN / KC)   // 32
#define TILE_M  64
#define GRID_M  256

// combine GEMM dims
#define KK      2176
#define KHALF   1088
#define NW      (NTC * FFTLEN)   // 393216
#define KSPLIT  8

typedef unsigned long long ull;
typedef __nv_bfloat16 bf16;
typedef __half fp16;

// ---------------- scratch ----------------
__device__ __align__(16) fp16  g_xh[XPAD];
__device__ __align__(16) fp16  g_Wf[NW];
__device__ __align__(16) bf16  g_Ah[2048 * KK];
__device__ __align__(16) bf16  g_Al[2048 * KK];
__device__ __align__(16) bf16  g_Bh[NTC * KK];
__device__ __align__(16) bf16  g_Bl[NTC * KK];
__device__ __align__(16) float g_Wpart[KSPLIT * NW];

// ---------------- base-ISA PTX helpers ----------------
__device__ __forceinline__ uint32_t smem_u32(const void* p) {
    uint32_t a;
    asm("{ .reg .u64 t; cvta.to.shared.u64 t, %1; cvt.u32.u64 %0, t; }" : "=r"(a) : "l"(p));
    return a;
}

#define MBAR_INIT(addr, cnt) \
    asm volatile("mbarrier.init.shared.b64 [%0], %1;" :: "r"((uint32_t)(addr)), "r"((uint32_t)(cnt)) : "memory")
#define MBAR_INVAL(addr) \
    asm volatile("mbarrier.inval.shared.b64 [%0];" :: "r"((uint32_t)(addr)) : "memory")
#define MBAR_ARRIVE(addr) \
    asm volatile("mbarrier.arrive.shared.b64 _, [%0];" :: "r"((uint32_t)(addr)) : "memory")
#define MBAR_EXPECT_TX(addr, bytes) \
    asm volatile("mbarrier.arrive.expect_tx.shared.b64 _, [%0], %1;" \
        :: "r"((uint32_t)(addr)), "r"((uint32_t)(bytes)) : "memory")

#define WAITP(mbar, ph) do { \
    uint32_t _m = (uint32_t)(mbar); uint32_t _p = (uint32_t)(ph); uint32_t _d; \
    asm volatile("{\n\t.reg .pred p;\n\t" \
        "mbarrier.try_wait.parity.acquire.cta.shared::cta.b64 p, [%1], %2;\n\t" \
        "selp.b32 %0, 1, 0, p;\n\t}" : "=r"(_d) : "r"(_m), "r"(_p) : "memory"); \
    if (!_d) { \
        asm volatile("{\n\t.reg .pred P1;\n\t" \
            "WL_%=:\n\t" \
            "mbarrier.try_wait.parity.acquire.cta.shared::cta.b64 P1, [%0], %1, 0x989680;\n\t" \
            "@P1 bra.uni WD_%=;\n\t" \
            "bra.uni WL_%=;\n\t" \
            "WD_%=:\n\t}" :: "r"(_m), "r"(_p) : "memory"); \
    } } while (0)

#define TMA2D(dst, map, x0, y0, mb) \
    asm volatile("cp.async.bulk.tensor.2d.shared::cta.global.tile.mbarrier::complete_tx::bytes " \
        "[%0], [%1, {%2, %3}], [%4];" \
        :: "r"((uint32_t)(dst)), "l"(map), "r"((int)(x0)), "r"((int)(y0)), "r"((uint32_t)(mb)) : "memory")

__device__ __forceinline__ void ldsm4(uint32_t* r, uint32_t addr) {
    asm volatile("ldmatrix.sync.aligned.m8n8.x4.shared.b16 {%0,%1,%2,%3}, [%4];"
        : "=r"(r[0]), "=r"(r[1]), "=r"(r[2]), "=r"(r[3]) : "r"(addr));
}
__device__ __forceinline__ void mma_bf16(float* c, const uint32_t* a, const uint32_t* b) {
    asm volatile("mma.sync.aligned.m16n8k16.row.col.f32.bf16.bf16.f32 "
        "{%0,%1,%2,%3}, {%4,%5,%6,%7}, {%8,%9}, {%0,%1,%2,%3};"
        : "+f"(c[0]), "+f"(c[1]), "+f"(c[2]), "+f"(c[3])
        : "r"(a[0]), "r"(a[1]), "r"(a[2]), "r"(a[3]), "r"(b[0]), "r"(b[1]));
}
__device__ __forceinline__ void mma_fp16(float* c, const uint32_t* a, const uint32_t* b) {
    asm volatile("mma.sync.aligned.m16n8k16.row.col.f32.f16.f16.f32 "
        "{%0,%1,%2,%3}, {%4,%5,%6,%7}, {%8,%9}, {%0,%1,%2,%3};"
        : "+f"(c[0]), "+f"(c[1]), "+f"(c[2]), "+f"(c[3])
        : "r"(a[0]), "r"(a[1]), "r"(a[2]), "r"(a[3]), "r"(b[0]), "r"(b[1]));
}

// ======================================================================
// Kernel 1 (merged prep): atrans | bbuild | xconvert in one launch
// ======================================================================
#define ATR_BLKS  4352          // 64 * 68
#define BB_BLKS   1728          // 9 * 192
#define XS_BLKS   8194
#define PREP_BLKS (ATR_BLKS + BB_BLKS + XS_BLKS)

__global__ __launch_bounds__(256) void prep_kernel(
    const float* __restrict__ x,
    const float* __restrict__ wcos, const float* __restrict__ wsin,
    const float* __restrict__ kr,   const float* __restrict__ ki)
{
    __shared__ float t[32][33];
    const int blk = blockIdx.x;
    const int tid = threadIdx.x;

    if (blk < ATR_BLKS) {
        const int tx = tid & 31, ty = tid >> 5;
        const int m0 = (blk & 63) * 32;
        const int bj = blk >> 6;
        const float* src;
        int srow0, kk0;
        if (bj < 34) { src = wcos; srow0 = bj * 32;        kk0 = bj * 32; }
        else         { src = wsin; srow0 = (bj - 34) * 32; kk0 = KHALF + (bj - 34) * 32; }
        #pragma unroll
        for (int i = 0; i < 4; i++) {
            const int r  = ty + i * 8;
            const int sr = srow0 + r;
            t[r][tx] = (sr < FB) ? src[sr * FFTLEN + m0 + tx] : 0.f;
        }
        __syncthreads();
        #pragma unroll
        for (int i = 0; i < 4; i++) {
            const int m = m0 + ty + i * 8;
            const float v = t[tx][ty + i * 8];
            bf16 h = __float2bfloat16(v);
            g_Ah[m * KK + kk0 + tx] = h;
            g_Al[m * KK + kk0 + tx] = __float2bfloat16(v - __bfloat162float(h));
        }
    } else if (blk < ATR_BLKS + BB_BLKS) {
        const int b2  = blk - ATR_BLKS;
        const int kk  = (b2 % 9) * 256 + tid;
        const int row = b2 / 9;
        if (kk >= KK) return;
        float v = 0.f;
        if (row < NBINS) {
            if (kk < FB)                             v =  kr[row * FB + kk];
            else if (kk >= KHALF && kk < KHALF + FB) v = -ki[row * FB + kk - KHALF];
        } else if (row < 2 * NBINS) {
            const int j = row - NBINS;
            if (kk < FB)                             v =  ki[j * FB + kk];
            else if (kk >= KHALF && kk < KHALF + FB) v =  kr[j * FB + kk - KHALF];
        }
        bf16 h = __float2bfloat16(v);
        g_Bh[row * KK + kk] = h;
        g_Bl[row * KK + kk] = __float2bfloat16(v - __bfloat162float(h));
    } else {
        const int i = ((blk - ATR_BLKS - BB_BLKS) * 256 + tid) * 4;
        if (i >= XPAD) return;
        float v[4];
        if (i + 4 <= TS) {
            float4 q = *(const float4*)(x + i);
            v[0] = q.x; v[1] = q.y; v[2] = q.z; v[3] = q.w;
        } else {
            #pragma unroll
            for (int j = 0; j < 4; j++) v[j] = (i + j < TS) ? x[i + j] : 0.f;
        }
        union { fp16 h[4]; uint2 u; } H;
        #pragma unroll
        for (int j = 0; j < 4; j++) H.h[j] = __float2half(v[j]);
        *(uint2*)&g_xh[i] = H.u;
    }
}

// ======================================================================
// Kernel 2: combine GEMM Wt = A' @ B'^T  (bf16 3-product), K-split x8
// ======================================================================
#define CSTAGE     3
#define CSTG_SZ    32768
#define CSTAGE0    1024
#define CSMEM      (CSTAGE0 + CSTAGE * CSTG_SZ)
#define CCHB       32768

__device__ __forceinline__ void issue_chunk_c(
    uint32_t sb, int s, int m0, int kc,
    const void* tAh, const void* tAl, const void* tBh, const void* tBl)
{
    const uint32_t mb = sb + s * 16;
    const uint32_t st = sb + CSTAGE0 + s * CSTG_SZ;
    MBAR_EXPECT_TX(mb, CCHB);
    TMA2D(st,         tAh, kc * 32, m0, mb);
    TMA2D(st + 4096,  tAl, kc * 32, m0, mb);
    TMA2D(st + 8192,  tBh, kc * 32, 0, mb);
    TMA2D(st + 20480, tBl, kc * 32, 0, mb);
}

__global__ __launch_bounds__(256, 2) void comb_mma_kernel(
    const __grid_constant__ CUtensorMap tmAh,
    const __grid_constant__ CUtensorMap tmAl,
    const __grid_constant__ CUtensorMap tmBh,
    const __grid_constant__ CUtensorMap tmBl)
{
    extern __shared__ __align__(1024) char smem[];
    const uint32_t sb = smem_u32(smem);
    const int tid  = threadIdx.x;
    const int wid  = tid >> 5;
    const int lane = tid & 31;
    const int wm   = wid & 1;
    const int wn   = wid >> 1;
    const int m0   = blockIdx.x * TILE_M;
    const int sp   = blockIdx.y;
    const int nch  = (sp < 4) ? 9 : 8;
    const int ksb  = (sp < 4) ? sp * 9 : 36 + (sp - 4) * 8;

    const int arow  = wm * 32 + (lane & 15);
    const int akb   = (lane >> 4) * 16;
    const int aswz  = ((arow >> 1) & 3) << 4;
    const int abase = arow * 64;
    const int brown = (lane & 7) + ((lane & 16) ? 8 : 0);
    const int bkb   = (lane & 8) ? 16 : 0;
    const int bswz  = ((brown >> 1) & 3) << 4;
    const int bbase = (wn * 48 + brown) * 64;

    if (tid == 0) {
        #pragma unroll
        for (int s = 0; s < CSTAGE; s++) {
            MBAR_INIT(sb + s * 16, 1);
            MBAR_INIT(sb + s * 16 + 8, 256);
        }
    }
    __syncthreads();
    if (tid == 0) {
        #pragma unroll
        for (int s = 0; s < CSTAGE; s++)
            issue_chunk_c(sb, s, m0, ksb + s, &tmAh, &tmAl, &tmBh, &tmBl);
    }

    float acc[2][6][4];
    #pragma unroll
    for (int t = 0; t < 2; t++)
        #pragma unroll
        for (int j = 0; j < 6; j++)
            #pragma unroll
            for (int q = 0; q < 4; q++) acc[t][j][q] = 0.f;

    int fph[CSTAGE] = {0, 0, 0};
    int eph[CSTAGE] = {0, 0, 0};

    for (int c = 0; c < nch; ++c) {
        const int s = c % CSTAGE;
        WAITP(sb + s * 16, fph[s]); fph[s] ^= 1;
        const uint32_t st = sb + CSTAGE0 + s * CSTG_SZ;

        #pragma unroll
        for (int ks = 0; ks < 2; ++ks) {
            uint32_t ah[2][4], alr[2][4], bh[6][2], blr[6][2];
            #pragma unroll
            for (int t = 0; t < 2; ++t) {
                const uint32_t ao = abase + t * 1024 + ((ks * 32 + akb) ^ aswz);
                ldsm4(ah[t],  st + ao);
                ldsm4(alr[t], st + 4096 + ao);
            }
            #pragma unroll
            for (int j2 = 0; j2 < 3; ++j2) {
                const uint32_t bo = bbase + j2 * 1024 + ((ks * 32 + bkb) ^ bswz);
                uint32_t r4[4];
                ldsm4(r4, st + 8192 + bo);
                bh[2*j2][0] = r4[0]; bh[2*j2][1] = r4[1];
                bh[2*j2+1][0] = r4[2]; bh[2*j2+1][1] = r4[3];
                ldsm4(r4, st + 20480 + bo);
                blr[2*j2][0] = r4[0]; blr[2*j2][1] = r4[1];
                blr[2*j2+1][0] = r4[2]; blr[2*j2+1][1] = r4[3];
            }
            #pragma unroll
            for (int t = 0; t < 2; ++t)
                #pragma unroll
                for (int j = 0; j < 6; ++j) {
                    mma_bf16(acc[t][j], ah[t],  bh[j]);
                    mma_bf16(acc[t][j], ah[t],  blr[j]);
                    mma_bf16(acc[t][j], alr[t], bh[j]);
                }
        }

        MBAR_ARRIVE(sb + s * 16 + 8);
        if (tid == 0 && c + CSTAGE < nch) {
            WAITP(sb + s * 16 + 8, eph[s]); eph[s] ^= 1;
            issue_chunk_c(sb, s, m0, ksb + c + CSTAGE, &tmAh, &tmAl, &tmBh, &tmBl);
        }
    }

    __syncthreads();
    float* Cs = (float*)(smem + CSTAGE0);   // [192][68]
    const int g  = lane >> 2;
    const int tc = lane & 3;
    #pragma unroll
    for (int t = 0; t < 2; ++t) {
        const int r0 = wm * 32 + t * 16 + g;
        #pragma unroll
        for (int j = 0; j < 6; ++j) {
            const int col = wn * 48 + j * 8 + tc * 2;
            Cs[col * 68 + r0]           = acc[t][j][0];
            Cs[(col + 1) * 68 + r0]     = acc[t][j][1];
            Cs[col * 68 + r0 + 8]       = acc[t][j][2];
            Cs[(col + 1) * 68 + r0 + 8] = acc[t][j][3];
        }
    }
    __syncthreads();
    float* dst = g_Wpart + sp * NW;
    #pragma unroll
    for (int i = tid; i < NTC * TILE_M; i += 256) {
        const int bin = i >> 6;
        const int r   = i & 63;
        dst[bin * FFTLEN + m0 + r] = Cs[bin * 68 + r];
    }

    __syncthreads();
    if (tid == 0) {
        #pragma unroll
        for (int s = 0; s < CSTAGE; s++) { MBAR_INVAL(sb + s * 16); MBAR_INVAL(sb + s * 16 + 8); }
    }
}

// ======================================================================
// Kernel 3: reduce 8 partials -> fp16 W
// ======================================================================
__global__ __launch_bounds__(256) void wconvert_kernel() {
    const int i = (blockIdx.x * 256 + threadIdx.x) * 4;
    if (i >= NW) return;
    float4 s = *(const float4*)&g_Wpart[i];
    #pragma unroll
    for (int p = 1; p < KSPLIT; p++) {
        float4 q = *(const float4*)&g_Wpart[p * NW + i];
        s.x += q.x; s.y += q.y; s.z += q.z; s.w += q.w;
    }
    union { fp16 h[4]; uint2 u; } H;
    H.h[0] = __float2half(s.x); H.h[1] = __float2half(s.y);
    H.h[2] = __float2half(s.z); H.h[3] = __float2half(s.w);
    *(uint2*)&g_Wf[i] = H.u;
}

// ======================================================================
// Kernel 4: main fp16 GEMM + magnitude; KC=64, SW128, 3x32KB stages,
//   256 threads (2M x 4N warps), warp-rotated TMA issuance,
//   per-warp empty arrivals (count 8)
// ======================================================================
#define MSTAGE   3
#define MSTG_SZ  32768
#define MSTAGE0  1024
#define MSMEM    (MSTAGE0 + MSTAGE * MSTG_SZ)   // 99328
#define MCHB     32768

__device__ __forceinline__ void issue_chunk_m(
    uint32_t sb, int s, int f0, int c,
    const void* tX, const void* tW)
{
    const uint32_t mb = sb + s * 16;
    const uint32_t st = sb + MSTAGE0 + s * MSTG_SZ;
    const int kx = (c & 7) * 64;        // inner offset within 512
    const int ky = f0 + (c >> 3);
    MBAR_EXPECT_TX(mb, MCHB);
    TMA2D(st,        tX, kx, ky, mb);
    TMA2D(st + 8192, tW, c * 64, 0, mb);
}

__global__ __launch_bounds__(256, 2) void cqt_mma_kernel(
    const __grid_constant__ CUtensorMap tmX,
    const __grid_constant__ CUtensorMap tmW,
    float* __restrict__ out)
{
    extern __shared__ __align__(1024) char smem[];
    const uint32_t sb = smem_u32(smem);
    const int tid  = threadIdx.x;
    const int wid  = tid >> 5;
    const int lane = tid & 31;
    const int wm   = wid & 1;        // 2 m-warps
    const int wn   = wid >> 1;       // 4 n-warps x 48 cols
    const int f0   = blockIdx.x * TILE_M;

    // 128B-row SW128 swizzle geometry: addr = row*128 + (col ^ ((row&7)<<4))
    const int arow  = wm * 32 + (lane & 15);
    const int akb   = (lane >> 4) * 16;            // k-half byte offset
    const int aswz  = (arow & 7) << 4;
    const int abase = arow * 128;
    const int brown = (lane & 7) + ((lane & 16) ? 8 : 0);
    const int bkb   = (lane & 8) ? 16 : 0;
    const int bswz  = (brown & 7) << 4;
    const int bbase0 = (wn * 48 + brown) * 128;

    if (tid == 0) {
        #pragma unroll
        for (int s = 0; s < MSTAGE; s++) {
            MBAR_INIT(sb + s * 16, 1);      // full (tx-based)
            MBAR_INIT(sb + s * 16 + 8, 8);  // empty: 1 arrive per warp
        }
    }
    __syncthreads();
    if (tid == 0) {
        #pragma unroll
        for (int s = 0; s < MSTAGE; s++)
            issue_chunk_m(sb, s, f0, s, &tmX, &tmW);
    }

    float acc[2][6][4];
    #pragma unroll
    for (int t = 0; t < 2; t++)
        #pragma unroll
        for (int j = 0; j < 6; j++)
            #pragma unroll
            for (int q = 0; q < 4; q++) acc[t][j][q] = 0.f;

    int fph[MSTAGE] = {0, 0, 0};
    int eph[MSTAGE] = {0, 0, 0};

    for (int c = 0; c < NCHUNK; ++c) {
        const int s = c % MSTAGE;
        WAITP(sb + s * 16, fph[s]); fph[s] ^= 1;
        const uint32_t st = sb + MSTAGE0 + s * MSTG_SZ;

        #pragma unroll
        for (int ks = 0; ks < 4; ++ks) {
            uint32_t ah[2][4], bh[6][2];
            #pragma unroll
            for (int t = 0; t < 2; ++t) {
                const uint32_t ao = abase + t * 2048 + ((ks * 32 + akb) ^ aswz);
                ldsm4(ah[t], st + ao);
            }
            #pragma unroll
            for (int j2 = 0; j2 < 3; ++j2) {
                const uint32_t bo = bbase0 + j2 * 2048 + ((ks * 32 + bkb) ^ bswz);
                uint32_t r4[4];
                ldsm4(r4, st + 8192 + bo);
                bh[2*j2][0] = r4[0]; bh[2*j2][1] = r4[1];
                bh[2*j2+1][0] = r4[2]; bh[2*j2+1][1] = r4[3];
            }
            #pragma unroll
            for (int t = 0; t < 2; ++t)
                #pragma unroll
                for (int j = 0; j < 6; ++j)
                    mma_fp16(acc[t][j], ah[t], bh[j]);
        }

        // stage consumed by this warp (ldsm done) -> per-warp arrive (count 8)
        if (lane == 0) MBAR_ARRIVE(sb + s * 16 + 8);
        // rotated producer: warp (c & 7) refills this stage
        const int cn = c + MSTAGE;
        if (cn < NCHUNK && wid == (c & 7) && lane == 0) {
            WAITP(sb + s * 16 + 8, eph[s]);
            issue_chunk_m(sb, s, f0, cn, &tmX, &tmW);
        }
        eph[s] ^= 1;
    }

    // ---------------- epilogue ----------------
    __syncthreads();
    float* Cs = (float*)(smem + MSTAGE0);   // [192][68]
    const int g  = lane >> 2;
    const int tc = lane & 3;
    #pragma unroll
    for (int t = 0; t < 2; ++t) {
        const int r0 = wm * 32 + t * 16 + g;
        #pragma unroll
        for (int j = 0; j < 6; ++j) {
            const int col = wn * 48 + j * 8 + tc * 2;
            Cs[col * 68 + r0]           = acc[t][j][0];
            Cs[(col + 1) * 68 + r0]     = acc[t][j][1];
            Cs[col * 68 + r0 + 8]       = acc[t][j][2];
            Cs[(col + 1) * 68 + r0 + 8] = acc[t][j][3];
        }
    }
    __syncthreads();
    #pragma unroll
    for (int i = tid; i < NBINS * TILE_M; i += 256) {
        const int bin = i >> 6;
        const int r   = i & 63;
        const int f   = f0 + r;
        if (f < NF) {
            const float re = Cs[bin * 68 + r];
            const float im = Cs[(bin + NBINS) * 68 + r];
            out[bin * NF + f] = sqrtf(re * re + im * im);
        }
    }

    __syncthreads();
    if (tid == 0) {
        #pragma unroll
        for (int s = 0; s < MSTAGE; s++) { MBAR_INVAL(sb + s * 16); MBAR_INVAL(sb + s * 16 + 8); }
    }
}

// ======================================================================
// host side
// ======================================================================
typedef CUresult (CUDAAPI *EncodeFn)(
    CUtensorMap*, CUtensorMapDataType, cuuint32_t, void*,
    const cuuint64_t*, const cuuint64_t*, const cuuint32_t*, const cuuint32_t*,
    CUtensorMapInterleave, CUtensorMapSwizzle, CUtensorMapL2promotion,
    CUtensorMapFloatOOBfill);

static void encode_2d(EncodeFn enc, CUtensorMap* tm, void* ptr,
                      CUtensorMapDataType dt, CUtensorMapSwizzle sw,
                      unsigned long long d0, unsigned long long d1,
                      unsigned long long strideB,
                      unsigned box0, unsigned box1) {
    cuuint64_t dims[2] = {d0, d1};
    cuuint64_t str[1]  = {strideB};
    cuuint32_t box[2]  = {box0, box1};
    cuuint32_t es[2]   = {1, 1};
    enc(tm, dt, 2, ptr, dims, str, box, es,
        CU_TENSOR_MAP_INTERLEAVE_NONE, sw,
        CU_TENSOR_MAP_L2_PROMOTION_L2_128B, CU_TENSOR_MAP_FLOAT_OOB_FILL_NONE);
}

extern "C" void kernel_launch(void* const* d_in, const int* in_sizes, int n_in,
                              void* d_out, int out_size) {
    const float* x    = (const float*)d_in[0];
    const float* wcos = (const float*)d_in[1];
    const float* wsin = (const float*)d_in[2];
    const float* kr   = (const float*)d_in[3];
    const float* ki   = (const float*)d_in[4];
    float* out = (float*)d_out;

    void* fn = nullptr;
    cudaDriverEntryPointQueryResult st;
#if CUDART_VERSION >= 12050
    cudaGetDriverEntryPointByVersion("cuTensorMapEncodeTiled", &fn, 12000,
                                     cudaEnableDefault, &st);
#else
    cudaGetDriverEntryPoint("cuTensorMapEncodeTiled", &fn, cudaEnableDefault, &st);
#endif
    EncodeFn enc = (EncodeFn)fn;

    void *pxh, *pwf, *pah, *pal, *pbh, *pbl;
    cudaGetSymbolAddress(&pxh, g_xh);
    cudaGetSymbolAddress(&pwf, g_Wf);
    cudaGetSymbolAddress(&pah, g_Ah);
    cudaGetSymbolAddress(&pal, g_Al);
    cudaGetSymbolAddress(&pbh, g_Bh);
    cudaGetSymbolAddress(&pbl, g_Bl);

    CUtensorMap tmX, tmW, tmAh, tmAl, tmBh, tmBl;
    // main GEMM: SW128, 64-elem (128B) boxes
    encode_2d(enc, &tmX, pxh, CU_TENSOR_MAP_DATA_TYPE_FLOAT16, CU_TENSOR_MAP_SWIZZLE_128B,
              512, 16387, 512ull * 2, 64, TILE_M);
    encode_2d(enc, &tmW, pwf, CU_TENSOR_MAP_DATA_TYPE_FLOAT16, CU_TENSOR_MAP_SWIZZLE_128B,
              FFTLEN, NTC, (unsigned long long)FFTLEN * 2, 64, NTC);
    // combine GEMM: SW64, 32-elem boxes (unchanged from R7)
    encode_2d(enc, &tmAh, pah, CU_TENSOR_MAP_DATA_TYPE_BFLOAT16, CU_TENSOR_MAP_SWIZZLE_64B,
              KK, 2048, (unsigned long long)KK * 2, 32, TILE_M);
    encode_2d(enc, &tmAl, pal, CU_TENSOR_MAP_DATA_TYPE_BFLOAT16, CU_TENSOR_MAP_SWIZZLE_64B,
              KK, 2048, (unsigned long long)KK * 2, 32, TILE_M);
    encode_2d(enc, &tmBh, pbh, CU_TENSOR_MAP_DATA_TYPE_BFLOAT16, CU_TENSOR_MAP_SWIZZLE_64B,
              KK, NTC, (unsigned long long)KK * 2, 32, NTC);
    encode_2d(enc, &tmBl, pbl, CU_TENSOR_MAP_DATA_TYPE_BFLOAT16, CU_TENSOR_MAP_SWIZZLE_64B,
              KK, NTC, (unsigned long long)KK * 2, 32, NTC);

    cudaFuncSetAttribute(cqt_mma_kernel,
                         cudaFuncAttributeMaxDynamicSharedMemorySize, MSMEM);
    cudaFuncSetAttribute(comb_mma_kernel,
                         cudaFuncAttributeMaxDynamicSharedMemorySize, CSMEM);

    prep_kernel<<<PREP_BLKS, 256>>>(x, wcos, wsin, kr, ki);
    comb_mma_kernel<<<dim3(32, KSPLIT), 256, CSMEM>>>(tmAh, tmAl, tmBh, tmBl);
    wconvert_kernel<<<NW / 1024, 256>>>();
    cqt_mma_kernel<<<GRID_M, 256, MSMEM>>>(tmX, tmW, out);
}